// round 5
// baseline (speedup 1.0000x reference)
#include <cuda_runtime.h>
#include <cuda_bf16.h>

// MeshNN: u(x) = linear interp of fused weights W = [w_dd0, w_uu..., w_dd1]
// on a UNIFORM 512-node grid (coords = linspace). Analytic node positions:
//   tg = (x - c0) * inv_h;  j = clamp(floor(tg));  t = tg - j;
//   u = W[j] + t*(W[j+1]-W[j])
// Scalar layout (1 pt/thread, 262144 threads) maximizes warp count for DRAM
// latency hiding; weight table staged in smem overlapping the x DRAM load.

#define NP_NODES 512

__global__ __launch_bounds__(256) void meshnn_kernel(
    const float* __restrict__ x,
    const float* __restrict__ coords,
    const float* __restrict__ w_uu,
    const float* __restrict__ w_dd,
    float*       __restrict__ out,
    int n)
{
    __shared__ float wsh[NP_NODES];

    int gid = blockIdx.x * blockDim.x + threadIdx.x;

    // Issue the DRAM load for x first so it overlaps the weight staging.
    float xf = 0.0f;
    if (gid < n) xf = __ldg(&x[gid]);

    // Stage fused weight vector into shared (2 coalesced iterations).
    #pragma unroll
    for (int it = 0; it < NP_NODES / 256; it++) {
        int i = it * 256 + threadIdx.x;
        float w;
        if (i == 0)                 w = __ldg(&w_dd[0]);
        else if (i == NP_NODES - 1) w = __ldg(&w_dd[1]);
        else                        w = __ldg(&w_uu[i - 1]);
        wsh[i] = w;
    }

    const float c0    = __ldg(&coords[0]);
    const float cL    = __ldg(&coords[NP_NODES - 1]);
    const float inv_h = (float)(NP_NODES - 1) / (cL - c0);

    __syncthreads();
    if (gid >= n) return;

    float tg = (xf - c0) * inv_h;
    int j = min(max((int)tg, 0), NP_NODES - 2);
    float t = tg - (float)j;

    float a = wsh[j];
    float b = wsh[j + 1];

    out[gid] = fmaf(t, b - a, a);
}

extern "C" void kernel_launch(void* const* d_in, const int* in_sizes, int n_in,
                              void* d_out, int out_size)
{
    const float* x      = (const float*)d_in[0];
    const float* coords = (const float*)d_in[1];
    const float* w_uu   = (const float*)d_in[2];
    const float* w_dd   = (const float*)d_in[3];
    float* out = (float*)d_out;

    int n = in_sizes[0];   // 262144
    int threads = 256;
    int blocks  = (n + threads - 1) / threads;   // 1024
    meshnn_kernel<<<blocks, threads>>>(x, coords, w_uu, w_dd, out, n);
}